// round 13
// baseline (speedup 1.0000x reference)
#include <cuda_runtime.h>
#include <cstdint>

#define H 4096
#define NUM_LAYERS 8
#define NBLOCKS 256
#define NTHREADS 512           // 16 warps -> 4096 warps == one per row
#define WARPS (NTHREADS / 32)
#define CHUNK 128              // rows per readiness chunk
#define NCHUNK (H / CHUNK)     // 32
#define GROUPS 8               // 8 groups x 4 chunks (512 cols) per row

// Ping-pong hidden-state buffers (allocation-free scratch).
__device__ float g_h[2][H];

// Per-layer, per-chunk completion counters (chunk full when == CHUNK).
// Reset to zero by the last block to finish, so every replay starts clean.
__device__ __align__(128) unsigned g_cnt[NUM_LAYERS][NCHUNK];
__device__ unsigned g_done = 0;

__device__ __forceinline__ uint4 ld_cv_v4(const unsigned* p) {
    uint4 v;
    asm volatile("ld.global.cv.v4.u32 {%0,%1,%2,%3}, [%4];"
                 : "=r"(v.x), "=r"(v.y), "=r"(v.z), "=r"(v.w) : "l"(p));
    return v;
}

// Persistent fused RNN with NO grid barrier: chunk-granular dataflow.
// Producers (layer l) publish h rows and bump a per-128-row counter.
// Consumers (layer l+1) walk their weight row in 8 fixed-order groups of
// 512 cols, spinning only until the 4 chunks feeding that group are full.
// A warp therefore waits for the 512 rows it needs NOW (not the global
// slowest row), layers overlap at chunk granularity, and DRAM streams
// through what used to be the barrier + x-restage seam.
__global__ void __launch_bounds__(NTHREADS, 2)
rnn_fused_kernel(const float* __restrict__ x,
                 const float* __restrict__ Wxh,
                 const float* __restrict__ bxh,
                 const float* __restrict__ bhh,
                 const float* __restrict__ fc_w,
                 const float* __restrict__ fc_b,
                 float* __restrict__ out) {
    const int warp = threadIdx.x >> 5;
    const int lane = threadIdx.x & 31;
    const int row  = blockIdx.x * WARPS + warp;   // 0..4095

    #pragma unroll 1
    for (int l = 0; l <= NUM_LAYERS; l++) {        // 8 tanh layers + fc
        const bool last = (l == NUM_LAYERS);
        const float* Wl = last ? fc_w : Wxh + (size_t)l * H * H;
        const float* xsrc = (l == 0) ? x : g_h[(l - 1) & 1];

        const float4* Wr = reinterpret_cast<const float4*>(Wl + (size_t)row * H);
        const float4* xv4 = reinterpret_cast<const float4*>(xsrc);

        float acc[4] = {0.f, 0.f, 0.f, 0.f};

        #pragma unroll 1
        for (int g = 0; g < GROUPS; g++) {
            // Wait until the 4 input chunks for this 512-col group are ready.
            if (l > 0) {
                const unsigned* cp = &g_cnt[l - 1][g * 4];
                uint4 c = ld_cv_v4(cp);
                if ((c.x & c.y & c.z & c.w) != CHUNK) {   // all must equal 128
                    while (true) {
                        c = ld_cv_v4(cp);
                        if (c.x == CHUNK && c.y == CHUNK &&
                            c.z == CHUNK && c.w == CHUNK) break;
                        __nanosleep(64);
                    }
                }
                __threadfence();   // acquire: order h reads after counter reads
            }

            // 4 weight LDG.128 + 4 x LDG.128 (x is L1/L2-hot), then FMA.
            float4 w[4], xr[4];
            #pragma unroll
            for (int j = 0; j < 4; j++)
                w[j] = Wr[lane + (g * 4 + j) * 32];
            #pragma unroll
            for (int j = 0; j < 4; j++)
                xr[j] = xv4[lane + (g * 4 + j) * 32];
            #pragma unroll
            for (int j = 0; j < 4; j++)
                acc[j] += w[j].x * xr[j].x + w[j].y * xr[j].y
                        + w[j].z * xr[j].z + w[j].w * xr[j].w;
        }

        float a = (acc[0] + acc[1]) + (acc[2] + acc[3]);
        #pragma unroll
        for (int off = 16; off; off >>= 1)
            a += __shfl_down_sync(0xffffffffu, a, off);

        if (lane == 0) {
            if (last) {
                out[row] = a + fc_b[row];
            } else {
                g_h[l & 1][row] = tanhf(a + bxh[l * H + row] + bhh[l * H + row]);
                __threadfence();                          // release h write
                atomicAdd(&g_cnt[l][row >> 7], 1u);       // publish chunk progress
            }
        }
    }

    // Cleanup: last block to finish resets all counters for the next replay
    // (kernel-completion ordering makes the reset visible to the next launch).
    __syncthreads();
    if (threadIdx.x == 0) {
        __threadfence();
        const unsigned old = atomicAdd(&g_done, 1u);
        if (old == NBLOCKS - 1) {
            #pragma unroll
            for (int l = 0; l < NUM_LAYERS; l++)
                #pragma unroll
                for (int c = 0; c < NCHUNK; c++)
                    g_cnt[l][c] = 0;
            g_done = 0;
            __threadfence();
        }
    }
}

extern "C" void kernel_launch(void* const* d_in, const int* in_sizes, int n_in,
                              void* d_out, int out_size) {
    const float* x    = (const float*)d_in[0];  // [1, H]
    const float* Wxh  = (const float*)d_in[1];  // [L, H, H]
    const float* bxh  = (const float*)d_in[2];  // [L, H]
    // d_in[3] = Whh — multiplied by a zero vector in the reference; never read.
    const float* bhh  = (const float*)d_in[4];  // [L, H]
    const float* fc_w = (const float*)d_in[5];  // [H, H]
    const float* fc_b = (const float*)d_in[6];  // [H]
    float* out = (float*)d_out;

    rnn_fused_kernel<<<NBLOCKS, NTHREADS>>>(x, Wxh, bxh, bhh, fc_w, fc_b, out);
}

// round 14
// speedup vs baseline: 1.5091x; 1.5091x over previous
#include <cuda_runtime.h>
#include <cstdint>

#define H 4096
#define NUM_LAYERS 8
#define NBLOCKS 256
#define NTHREADS 512          // 16 warps/block, 64 regs -> exactly 2 blocks/SM max
#define WARPS (NTHREADS / 32)
#define MAXSM 256

// Ping-pong hidden-state buffers (allocation-free scratch).
__device__ float g_h[2][H];

// Software grid-barrier state (monotonic across graph replays).
__device__ unsigned g_bar_count = 0;
__device__ unsigned g_bar_phase = 0;

// SM registration state (reset at kernel end for graph replays).
__device__ unsigned g_nsm_blocks[MAXSM];
__device__ unsigned g_sm_order_of[MAXSM];
__device__ unsigned g_sm_counter = 0;
__device__ unsigned g_done = 0;

__device__ __forceinline__ void grid_barrier() {
    __syncthreads();
    if (threadIdx.x == 0) {
        const unsigned target = *(volatile unsigned*)&g_bar_phase + 1;
        __threadfence();
        const unsigned old = atomicAdd(&g_bar_count, 1);
        if (old == NBLOCKS - 1) {
            *(volatile unsigned*)&g_bar_count = 0;
            __threadfence();
            atomicAdd(&g_bar_phase, 1);
        } else {
            while (*(volatile unsigned*)&g_bar_phase < target)
                __nanosleep(64);
        }
        __threadfence();
    }
    __syncthreads();
}

// One warp: dot(W[row,:], x_smem), batch-4 LDG.128 (R8-proven schedule).
__device__ __forceinline__ float row_dot(const float* __restrict__ W,
                                         const float4* __restrict__ sh4,
                                         int row, int lane) {
    const float4* Wr = reinterpret_cast<const float4*>(W + (size_t)row * H);
    float acc[4] = {0.f, 0.f, 0.f, 0.f};
    #pragma unroll
    for (int i = 0; i < 32; i += 4) {
        float4 w[4];
        #pragma unroll
        for (int j = 0; j < 4; j++)
            w[j] = Wr[lane + (i + j) * 32];
        #pragma unroll
        for (int j = 0; j < 4; j++) {
            float4 xv = sh4[lane + (i + j) * 32];
            acc[j] += w[j].x * xv.x + w[j].y * xv.y
                    + w[j].z * xv.z + w[j].w * xv.w;
        }
    }
    float a = (acc[0] + acc[1]) + (acc[2] + acc[3]);
    #pragma unroll
    for (int off = 16; off; off >>= 1)
        a += __shfl_down_sync(0xffffffffu, a, off);
    return a;
}

__device__ __forceinline__ void emit(int l, int row, float a,
                                     const float* bxh, const float* bhh,
                                     const float* fc_b, float* out, int lane) {
    if (lane != 0) return;
    if (l == NUM_LAYERS)
        out[row] = a + fc_b[row];
    else
        g_h[l & 1][row] = tanhf(a + bxh[l * H + row] + bhh[l * H + row]);
}

// Persistent fused RNN (R8 geometry: 256x512, 2 blocks/SM with seam overlap)
// + runtime per-SM row rebalance: blocks discover their SM via %smid and the
// 4096 rows/layer are split evenly over the physical SMs (27-28 rows each)
// instead of R8's 32-vs-16 imbalance. SMs hosting 2 blocks split their quota
// between the blocks; SMs hosting 1 block give each warp two sequential rows
// (per-SM bytes-in-flight unchanged). Row->value mapping is fixed, so output
// is bit-identical regardless of which SM computes which row.
__global__ void __launch_bounds__(NTHREADS, 2)
rnn_fused_kernel(const float* __restrict__ x,
                 const float* __restrict__ Wxh,
                 const float* __restrict__ bxh,
                 const float* __restrict__ bhh,
                 const float* __restrict__ fc_w,
                 const float* __restrict__ fc_b,
                 float* __restrict__ out) {
    __shared__ float4 sh4[H / 4];    // 16 KB: current input vector
    __shared__ int s_start, s_cnt, s_twoRows;

    const int warp = threadIdx.x >> 5;
    const int lane = threadIdx.x & 31;

    // ---- Registration: discover SM population (once per launch) ----
    if (threadIdx.x == 0) {
        unsigned smid;
        asm("mov.u32 %0, %%smid;" : "=r"(smid));
        const unsigned slot = atomicAdd(&g_nsm_blocks[smid], 1u);
        if (slot == 0)
            g_sm_order_of[smid] = atomicAdd(&g_sm_counter, 1u);
        __threadfence();
        s_start = (int)smid;      // stash smid
        s_cnt   = (int)slot;      // stash slot
    }
    grid_barrier();               // all registrations visible

    if (threadIdx.x == 0) {
        const unsigned smid = (unsigned)s_start;
        const unsigned slot = (unsigned)s_cnt;
        const unsigned S    = *(volatile unsigned*)&g_sm_counter;
        const unsigned nblk = *(volatile unsigned*)&g_nsm_blocks[smid];
        const unsigned ord  = *(volatile unsigned*)&g_sm_order_of[smid];
        const int rs = (int)(((unsigned long long)H * ord) / S);
        const int re = (int)(((unsigned long long)H * (ord + 1)) / S);
        const int cnt = re - rs;
        int start = rs, mycnt = 0, two = 0;
        if (nblk >= 2) {                      // split quota between 2 blocks
            const int half = (cnt + 1) / 2;
            if (slot == 0)      { start = rs;        mycnt = half; }
            else if (slot == 1) { start = rs + half; mycnt = cnt - half; }
            else                { mycnt = 0; }    // pathological 3rd block: idle
        } else {                              // single block: 2 rows per warp
            start = rs; mycnt = cnt; two = 1;
        }
        s_start = start; s_cnt = mycnt; s_twoRows = two;
    }
    __syncthreads();

    const int start = s_start, cnt = s_cnt, twoRows = s_twoRows;
    const int rowA = start + warp;
    const int rowB = start + WARPS + warp;
    const bool hasA = (warp < cnt) && (warp < WARPS);
    const bool hasB = twoRows && (WARPS + warp < cnt);

    const float* cur = x;

    #pragma unroll 1
    for (int l = 0; l <= NUM_LAYERS; l++) {       // 8 tanh layers + fc
        const bool last = (l == NUM_LAYERS);
        const float* Wl = last ? fc_w : Wxh + (size_t)l * H * H;

        // Stage this layer's input (16 KB) into shared memory.
        const float4* xg = reinterpret_cast<const float4*>(cur);
        #pragma unroll
        for (int i = threadIdx.x; i < H / 4; i += NTHREADS)
            sh4[i] = xg[i];
        __syncthreads();

        if (hasA) {
            const float a = row_dot(Wl, sh4, rowA, lane);
            emit(l, rowA, a, bxh, bhh, fc_b, out, lane);
        }
        if (hasB) {
            const float a = row_dot(Wl, sh4, rowB, lane);
            emit(l, rowB, a, bxh, bhh, fc_b, out, lane);
        }

        if (!last) {
            grid_barrier();           // publish h before anyone reads it
            cur = g_h[l & 1];
        }
    }

    // Cleanup: last block resets registration state for the next replay.
    __syncthreads();
    if (threadIdx.x == 0) {
        __threadfence();
        const unsigned old = atomicAdd(&g_done, 1u);
        if (old == NBLOCKS - 1) {
            for (int i = 0; i < MAXSM; i++) g_nsm_blocks[i] = 0;
            g_sm_counter = 0;
            g_done = 0;
            __threadfence();
        }
    }
}

extern "C" void kernel_launch(void* const* d_in, const int* in_sizes, int n_in,
                              void* d_out, int out_size) {
    const float* x    = (const float*)d_in[0];  // [1, H]
    const float* Wxh  = (const float*)d_in[1];  // [L, H, H]
    const float* bxh  = (const float*)d_in[2];  // [L, H]
    // d_in[3] = Whh — multiplied by a zero vector in the reference; never read.
    const float* bhh  = (const float*)d_in[4];  // [L, H]
    const float* fc_w = (const float*)d_in[5];  // [H, H]
    const float* fc_b = (const float*)d_in[6];  // [H]
    float* out = (float*)d_out;

    rnn_fused_kernel<<<NBLOCKS, NTHREADS>>>(x, Wxh, bxh, bhh, fc_w, fc_b, out);
}